// round 5
// baseline (speedup 1.0000x reference)
#include <cuda_runtime.h>
#include <cuda_bf16.h>

#define NEG_INF -1e10f
#define MAX_N 50176
#define TM 64        // nodes per gemm block
#define HS 132       // smem row stride (floats)
#define NCHUNK 5

// scratch for pooled neighbor features [N,128]
__device__ float g_H[MAX_N * 128];

// ---------------------------------------------------------------------------
// Kernel 1: masked neighbor max-pool (one warp per node) + fused self-relu
// ---------------------------------------------------------------------------
__global__ __launch_bounds__(256)
void pool_kernel(const float* __restrict__ self_vecs,   // [N,128]
                 const float* __restrict__ neigh,       // [N,32,128]
                 const int*   __restrict__ mask,        // [N,32]
                 float*       __restrict__ out,         // [N,256]
                 int node_begin, int node_end)
{
    const int gwarp = (blockIdx.x * blockDim.x + threadIdx.x) >> 5;
    const int lane  = threadIdx.x & 31;
    const int n = node_begin + gwarp;
    if (n >= node_end) return;

    // one mask element per lane -> ballot = 32-bit validity mask
    const int mv = mask[n * 32 + lane];
    const unsigned vm = __ballot_sync(0xffffffffu, mv > 0);

    float4 m = make_float4(NEG_INF, NEG_INF, NEG_INF, NEG_INF);
    const float4* np = reinterpret_cast<const float4*>(neigh + (size_t)n * 32 * 128) + lane;

    // fully unrolled, predicated loads: independent -> high MLP,
    // predicate-false rows issue no DRAM traffic.
    #pragma unroll
    for (int k = 0; k < 32; k++) {
        if ((vm >> k) & 1u) {
            float4 v = np[(size_t)k * 32];
            m.x = fmaxf(m.x, v.x);
            m.y = fmaxf(m.y, v.y);
            m.z = fmaxf(m.z, v.z);
            m.w = fmaxf(m.w, v.w);
        }
    }

    reinterpret_cast<float4*>(g_H + (size_t)n * 128)[lane] = m;

    // fused self path: relu(self) -> out[:, 0:128]
    float4 s = reinterpret_cast<const float4*>(self_vecs + (size_t)n * 128)[lane];
    s.x = fmaxf(s.x, 0.f); s.y = fmaxf(s.y, 0.f);
    s.z = fmaxf(s.z, 0.f); s.w = fmaxf(s.w, 0.f);
    reinterpret_cast<float4*>(out + (size_t)n * 256)[lane] = s;
}

// ---------------------------------------------------------------------------
// Kernel 2: out[:,128:256] = relu(H @ W), 64-node tile, 256 threads,
// 4x8 micro-tile -> ~60 regs -> 4 blocks/SM (50% occ)
// ---------------------------------------------------------------------------
__global__ __launch_bounds__(256, 4)
void gemm_kernel(const float* __restrict__ W,    // [128,128]
                 float*       __restrict__ out,  // [N,256]
                 int node_begin, int node_end)
{
    __shared__ float Hs[TM * HS];

    const int tid = threadIdx.x;
    const int n0  = node_begin + blockIdx.x * TM;

    // cooperative load of the 64x128 H tile (float4, coalesced)
    {
        const int nrows = min(TM, node_end - n0);
        #pragma unroll
        for (int it = 0; it < (TM * 32) / 256; it++) {
            const int idx = it * 256 + tid;         // 0 .. 2047
            const int row = idx >> 5;               // 0..63
            const int c4  = idx & 31;               // float4 column
            float4 v = (row < nrows)
                ? reinterpret_cast<const float4*>(g_H + (size_t)(n0 + row) * 128)[c4]
                : make_float4(0.f, 0.f, 0.f, 0.f);
            reinterpret_cast<float4*>(Hs + row * HS)[c4] = v;
        }
    }
    __syncthreads();

    const int tx = tid & 15;      // 0..15 -> 8 output cols each
    const int ty = tid >> 4;      // 0..15 -> 4 node rows each

    float acc[4][8];
    #pragma unroll
    for (int i = 0; i < 4; i++)
        #pragma unroll
        for (int j = 0; j < 8; j++)
            acc[i][j] = 0.f;

    const float* wbase = W + tx * 8;

    #pragma unroll 4
    for (int kk = 0; kk < 128; kk++) {
        float a[4];
        #pragma unroll
        for (int i = 0; i < 4; i++)
            a[i] = Hs[(ty * 4 + i) * HS + kk];

        const float4 b0 = __ldg(reinterpret_cast<const float4*>(wbase + kk * 128));
        const float4 b1 = __ldg(reinterpret_cast<const float4*>(wbase + kk * 128 + 4));

        #pragma unroll
        for (int i = 0; i < 4; i++) {
            acc[i][0] = fmaf(a[i], b0.x, acc[i][0]);
            acc[i][1] = fmaf(a[i], b0.y, acc[i][1]);
            acc[i][2] = fmaf(a[i], b0.z, acc[i][2]);
            acc[i][3] = fmaf(a[i], b0.w, acc[i][3]);
            acc[i][4] = fmaf(a[i], b1.x, acc[i][4]);
            acc[i][5] = fmaf(a[i], b1.y, acc[i][5]);
            acc[i][6] = fmaf(a[i], b1.z, acc[i][6]);
            acc[i][7] = fmaf(a[i], b1.w, acc[i][7]);
        }
    }

    #pragma unroll
    for (int i = 0; i < 4; i++) {
        const int n = n0 + ty * 4 + i;
        if (n < node_end) {
            float4 c0, c1;
            c0.x = fmaxf(acc[i][0], 0.f); c0.y = fmaxf(acc[i][1], 0.f);
            c0.z = fmaxf(acc[i][2], 0.f); c0.w = fmaxf(acc[i][3], 0.f);
            c1.x = fmaxf(acc[i][4], 0.f); c1.y = fmaxf(acc[i][5], 0.f);
            c1.z = fmaxf(acc[i][6], 0.f); c1.w = fmaxf(acc[i][7], 0.f);
            float* op = out + (size_t)n * 256 + 128 + tx * 8;
            reinterpret_cast<float4*>(op)[0] = c0;
            reinterpret_cast<float4*>(op)[1] = c1;
        }
    }
}

// lazily-created side stream + events (created on the first, uncaptured,
// correctness call; reused identically on every call -> deterministic work)
static cudaStream_t g_s2 = nullptr;
static cudaEvent_t  g_fork[NCHUNK];
static cudaEvent_t  g_join = nullptr;

extern "C" void kernel_launch(void* const* d_in, const int* in_sizes, int n_in,
                              void* d_out, int out_size)
{
    const float* self_vecs = (const float*)d_in[0];   // [N,128]
    const float* neigh     = (const float*)d_in[1];   // [N,32,128]
    const int*   mask      = (const int*)  d_in[2];   // [N,32]
    const float* W         = (const float*)d_in[3];   // [128,128]
    float* out = (float*)d_out;                        // [N,256]

    const int N = in_sizes[0] / 128;

    if (g_s2 == nullptr) {
        cudaStreamCreateWithFlags(&g_s2, cudaStreamNonBlocking);
        for (int c = 0; c < NCHUNK; c++)
            cudaEventCreateWithFlags(&g_fork[c], cudaEventDisableTiming);
        cudaEventCreateWithFlags(&g_join, cudaEventDisableTiming);
    }

    // chunk boundaries, multiples of TM(=64) except possibly the last
    int chunk = ((N + NCHUNK - 1) / NCHUNK + TM - 1) / TM * TM;

    for (int c = 0; c < NCHUNK; c++) {
        const int b = c * chunk;
        if (b >= N) {
            // still record events so the wait graph is well-formed
            cudaEventRecord(g_fork[c], 0);
            continue;
        }
        const int e = min(b + chunk, N);
        const int nodes = e - b;

        // pool chunk on main (capture) stream: 8 nodes per 256-thr block
        const int grid1 = (nodes + 7) / 8;
        pool_kernel<<<grid1, 256, 0, 0>>>(self_vecs, neigh, mask, out, b, e);
        cudaEventRecord(g_fork[c], 0);

        // gemm chunk on side stream, dependent on its pool chunk
        cudaStreamWaitEvent(g_s2, g_fork[c], 0);
        const int grid2 = (nodes + TM - 1) / TM;
        gemm_kernel<<<grid2, 256, 0, g_s2>>>(W, out, b, e);
    }

    // join side stream back into the capture stream
    cudaEventRecord(g_join, g_s2);
    cudaStreamWaitEvent(0, g_join, 0);
}

// round 9
// speedup vs baseline: 1.3693x; 1.3693x over previous
#include <cuda_runtime.h>
#include <cuda_bf16.h>

#define NEG_INF -1e10f
#define MAX_N 50176
#define TM 64        // nodes per gemm block
#define HS 132       // smem row stride (floats)

// scratch for pooled neighbor features [N,128]
__device__ float g_H[MAX_N * 128];

// packed f32x2 FMA: d = a*b + c (per 32-bit half), sm_103a FFMA2
#define FMA2(d, a, b, c) \
    asm("fma.rn.f32x2 %0, %1, %2, %3;" : "=l"(d) : "l"(a), "l"(b), "l"(c))
// duplicate one fp32 into both halves of a 64-bit f32x2
#define DUP2(d, s) \
    asm("mov.b64 %0, {%1, %1};" : "=l"(d) : "f"(s))

// ---------------------------------------------------------------------------
// Kernel 1: masked neighbor max-pool (one warp per node) + fused self-relu
// ---------------------------------------------------------------------------
__global__ __launch_bounds__(256)
void pool_kernel(const float* __restrict__ self_vecs,   // [N,128]
                 const float* __restrict__ neigh,       // [N,32,128]
                 const int*   __restrict__ mask,        // [N,32]
                 float*       __restrict__ out,         // [N,256]
                 int N)
{
    const int gwarp = (blockIdx.x * blockDim.x + threadIdx.x) >> 5;
    const int lane  = threadIdx.x & 31;
    if (gwarp >= N) return;
    const int n = gwarp;

    // one mask element per lane -> ballot = 32-bit validity mask
    const int mv = mask[n * 32 + lane];
    const unsigned vm = __ballot_sync(0xffffffffu, mv > 0);

    float4 m = make_float4(NEG_INF, NEG_INF, NEG_INF, NEG_INF);
    const float4* np = reinterpret_cast<const float4*>(neigh + (size_t)n * 32 * 128) + lane;

    // fully unrolled, predicated loads: independent -> high MLP,
    // predicate-false rows issue no DRAM traffic.
    #pragma unroll
    for (int k = 0; k < 32; k++) {
        if ((vm >> k) & 1u) {
            float4 v = np[(size_t)k * 32];
            m.x = fmaxf(m.x, v.x);
            m.y = fmaxf(m.y, v.y);
            m.z = fmaxf(m.z, v.z);
            m.w = fmaxf(m.w, v.w);
        }
    }

    reinterpret_cast<float4*>(g_H + (size_t)n * 128)[lane] = m;

    // fused self path: relu(self) -> out[:, 0:128]
    float4 s = reinterpret_cast<const float4*>(self_vecs + (size_t)n * 128)[lane];
    s.x = fmaxf(s.x, 0.f); s.y = fmaxf(s.y, 0.f);
    s.z = fmaxf(s.z, 0.f); s.w = fmaxf(s.w, 0.f);
    reinterpret_cast<float4*>(out + (size_t)n * 256)[lane] = s;
}

// ---------------------------------------------------------------------------
// Kernel 2: out[:,128:256] = relu(H @ W) using packed f32x2 FMA.
// 64-node tile, 256 threads as 16(ty) x 16(tx), 4 rows x 8 cols per thread,
// accumulators held as 4x4 f32x2 pairs.
// ---------------------------------------------------------------------------
__global__ __launch_bounds__(256, 4)
void gemm_kernel(const float* __restrict__ W,    // [128,128]
                 float*       __restrict__ out,  // [N,256]
                 int N)
{
    __shared__ float Hs[TM * HS];

    const int tid = threadIdx.x;
    const int n0  = blockIdx.x * TM;

    // cooperative load of the 64x128 H tile (float4, coalesced)
    {
        const int nrows = min(TM, N - n0);
        #pragma unroll
        for (int it = 0; it < (TM * 32) / 256; it++) {
            const int idx = it * 256 + tid;         // 0 .. 2047
            const int row = idx >> 5;               // 0..63
            const int c4  = idx & 31;               // float4 column
            float4 v = (row < nrows)
                ? reinterpret_cast<const float4*>(g_H + (size_t)(n0 + row) * 128)[c4]
                : make_float4(0.f, 0.f, 0.f, 0.f);
            reinterpret_cast<float4*>(Hs + row * HS)[c4] = v;
        }
    }
    __syncthreads();

    const int tx = tid & 15;      // 0..15 -> 8 output cols each
    const int ty = tid >> 4;      // 0..15 -> 4 node rows each

    // acc2[i][j] = (C[row_i][2j], C[row_i][2j+1]) packed as f32x2
    unsigned long long acc2[4][4];
    #pragma unroll
    for (int i = 0; i < 4; i++)
        #pragma unroll
        for (int j = 0; j < 4; j++)
            acc2[i][j] = 0ull;    // (0.0f, 0.0f)

    const float* wbase = W + tx * 8;

    #pragma unroll 4
    for (int kk = 0; kk < 128; kk++) {
        // broadcast LDS of 4 H rows, duplicated into f32x2
        unsigned long long ad[4];
        #pragma unroll
        for (int i = 0; i < 4; i++) {
            float av = Hs[(ty * 4 + i) * HS + kk];
            DUP2(ad[i], av);
        }

        // 8 W values for this k as 4 packed f32x2 (two LDG.128)
        const ulonglong2* wb = reinterpret_cast<const ulonglong2*>(wbase + (size_t)kk * 128);
        const ulonglong2 b01 = __ldg(wb);       // cols 0-3
        const ulonglong2 b23 = __ldg(wb + 1);   // cols 4-7

        #pragma unroll
        for (int i = 0; i < 4; i++) {
            FMA2(acc2[i][0], ad[i], b01.x, acc2[i][0]);
            FMA2(acc2[i][1], ad[i], b01.y, acc2[i][1]);
            FMA2(acc2[i][2], ad[i], b23.x, acc2[i][2]);
            FMA2(acc2[i][3], ad[i], b23.y, acc2[i][3]);
        }
    }

    // unpack, relu, store neighbor half
    #pragma unroll
    for (int i = 0; i < 4; i++) {
        const int n = n0 + ty * 4 + i;
        if (n < N) {
            float c[8];
            #pragma unroll
            for (int j = 0; j < 4; j++) {
                float lo, hi;
                asm("mov.b64 {%0, %1}, %2;" : "=f"(lo), "=f"(hi) : "l"(acc2[i][j]));
                c[2 * j]     = fmaxf(lo, 0.f);
                c[2 * j + 1] = fmaxf(hi, 0.f);
            }
            float* op = out + (size_t)n * 256 + 128 + tx * 8;
            reinterpret_cast<float4*>(op)[0] = make_float4(c[0], c[1], c[2], c[3]);
            reinterpret_cast<float4*>(op)[1] = make_float4(c[4], c[5], c[6], c[7]);
        }
    }
}

extern "C" void kernel_launch(void* const* d_in, const int* in_sizes, int n_in,
                              void* d_out, int out_size)
{
    const float* self_vecs = (const float*)d_in[0];   // [N,128]
    const float* neigh     = (const float*)d_in[1];   // [N,32,128]
    const int*   mask      = (const int*)  d_in[2];   // [N,32]
    const float* W         = (const float*)d_in[3];   // [128,128]
    float* out = (float*)d_out;                        // [N,256]

    const int N = in_sizes[0] / 128;

    // kernel 1: one warp per node (8 nodes per 256-thread block)
    const int grid1 = (N + 7) / 8;
    pool_kernel<<<grid1, 256>>>(self_vecs, neigh, mask, out, N);

    // kernel 2: 64-node tiles
    const int grid2 = (N + TM - 1) / TM;
    gemm_kernel<<<grid2, 256>>>(W, out, N);
}

// round 10
// speedup vs baseline: 1.9884x; 1.4521x over previous
#include <cuda_runtime.h>
#include <cuda_bf16.h>

#define NEG_INF -1e10f

// packed f32x2 FMA: d = a*b + c (per 32-bit half), sm_103a FFMA2
#define FMA2(d, a, b, c) \
    asm("fma.rn.f32x2 %0, %1, %2, %3;" : "=l"(d) : "l"(a), "l"(b), "l"(c))
// duplicate one fp32 into both halves of a 64-bit f32x2
#define DUP2(d, s) \
    asm("mov.b64 %0, {%1, %1};" : "=l"(d) : "f"(s))

// Fully fused, warp-autonomous kernel.
// Each warp owns 4 consecutive nodes:
//   phase A: masked max-pool (predicated streaming, high MLP) + self-relu copy,
//            pooled H staged to the warp's private smem slice
//   phase B: 4-node GEMM vs W[128,128]; lane computes 4 output columns for all
//            4 nodes; one coalesced W row read is shared by the 4 nodes.
// No __syncthreads anywhere -> warps drift out of phase, DRAM stays saturated
// while other warps issue FMA.
__global__ __launch_bounds__(256, 4)
void fused_kernel(const float* __restrict__ self_vecs,   // [N,128]
                  const float* __restrict__ neigh,       // [N,32,128]
                  const int*   __restrict__ mask,        // [N,32]
                  const float* __restrict__ W,           // [128,128]
                  float*       __restrict__ out,         // [N,256]
                  int N)
{
    // [warp][node][32] float4  = 8*4*32*16B = 16 KB
    __shared__ float4 Hs[8 * 4 * 32];

    const int tid  = threadIdx.x;
    const int lane = tid & 31;
    const int warp = tid >> 5;                    // 0..7
    const int n_base = (blockIdx.x * 8 + warp) * 4;

    // ---------------- Phase A: pool 4 nodes ----------------
    #pragma unroll
    for (int r = 0; r < 4; r++) {
        const int n = n_base + r;                 // uniform across warp
        float4 m = make_float4(0.f, 0.f, 0.f, 0.f);
        if (n < N) {
            m = make_float4(NEG_INF, NEG_INF, NEG_INF, NEG_INF);
            const int mv = mask[n * 32 + lane];
            const unsigned vm = __ballot_sync(0xffffffffu, mv > 0);

            const float4* np =
                reinterpret_cast<const float4*>(neigh + (size_t)n * 32 * 128) + lane;
            #pragma unroll
            for (int k = 0; k < 32; k++) {
                if ((vm >> k) & 1u) {
                    float4 v = np[(size_t)k * 32];
                    m.x = fmaxf(m.x, v.x);
                    m.y = fmaxf(m.y, v.y);
                    m.z = fmaxf(m.z, v.z);
                    m.w = fmaxf(m.w, v.w);
                }
            }

            // self path: relu(self) -> out[:, 0:128]
            float4 s = reinterpret_cast<const float4*>(self_vecs + (size_t)n * 128)[lane];
            s.x = fmaxf(s.x, 0.f); s.y = fmaxf(s.y, 0.f);
            s.z = fmaxf(s.z, 0.f); s.w = fmaxf(s.w, 0.f);
            reinterpret_cast<float4*>(out + (size_t)n * 256)[lane] = s;
        }
        Hs[(warp * 4 + r) * 32 + lane] = m;       // conflict-free STS.128
    }
    __syncwarp();

    // ---------------- Phase B: 4-node GEMM ----------------
    // lane -> output columns [lane*4, lane*4+4); acc packed as f32x2 pairs
    unsigned long long acc[4][2];
    #pragma unroll
    for (int r = 0; r < 4; r++) { acc[r][0] = 0ull; acc[r][1] = 0ull; }

    const float4* hbase = Hs + warp * 4 * 32;
    const float*  wcol  = W + lane * 4;

    #pragma unroll 4
    for (int k4 = 0; k4 < 32; k4++) {
        // 4 k-values for each of the 4 nodes (broadcast LDS.128)
        float4 h0 = hbase[0 * 32 + k4];
        float4 h1 = hbase[1 * 32 + k4];
        float4 h2 = hbase[2 * 32 + k4];
        float4 h3 = hbase[3 * 32 + k4];

        #pragma unroll
        for (int s = 0; s < 4; s++) {
            const int k = k4 * 4 + s;
            // W[k, lane*4 .. lane*4+3]: 16B per lane, 512B coalesced per warp,
            // ONE row read serves all 4 nodes.
            const ulonglong2 wv =
                __ldg(reinterpret_cast<const ulonglong2*>(wcol + (size_t)k * 128));

            const float a0 = (s == 0) ? h0.x : (s == 1) ? h0.y : (s == 2) ? h0.z : h0.w;
            const float a1 = (s == 0) ? h1.x : (s == 1) ? h1.y : (s == 2) ? h1.z : h1.w;
            const float a2 = (s == 0) ? h2.x : (s == 1) ? h2.y : (s == 2) ? h2.z : h2.w;
            const float a3 = (s == 0) ? h3.x : (s == 1) ? h3.y : (s == 2) ? h3.z : h3.w;

            unsigned long long d0, d1, d2, d3;
            DUP2(d0, a0); DUP2(d1, a1); DUP2(d2, a2); DUP2(d3, a3);

            FMA2(acc[0][0], d0, wv.x, acc[0][0]);
            FMA2(acc[0][1], d0, wv.y, acc[0][1]);
            FMA2(acc[1][0], d1, wv.x, acc[1][0]);
            FMA2(acc[1][1], d1, wv.y, acc[1][1]);
            FMA2(acc[2][0], d2, wv.x, acc[2][0]);
            FMA2(acc[2][1], d2, wv.y, acc[2][1]);
            FMA2(acc[3][0], d3, wv.x, acc[3][0]);
            FMA2(acc[3][1], d3, wv.y, acc[3][1]);
        }
    }

    // unpack, relu, store neighbor half: out[n, 128 + lane*4 .. +3]
    #pragma unroll
    for (int r = 0; r < 4; r++) {
        const int n = n_base + r;
        if (n < N) {
            float c0, c1, c2, c3;
            asm("mov.b64 {%0, %1}, %2;" : "=f"(c0), "=f"(c1) : "l"(acc[r][0]));
            asm("mov.b64 {%0, %1}, %2;" : "=f"(c2), "=f"(c3) : "l"(acc[r][1]));
            float4 cv;
            cv.x = fmaxf(c0, 0.f); cv.y = fmaxf(c1, 0.f);
            cv.z = fmaxf(c2, 0.f); cv.w = fmaxf(c3, 0.f);
            reinterpret_cast<float4*>(out + (size_t)n * 256 + 128)[lane] = cv;
        }
    }
}

extern "C" void kernel_launch(void* const* d_in, const int* in_sizes, int n_in,
                              void* d_out, int out_size)
{
    const float* self_vecs = (const float*)d_in[0];   // [N,128]
    const float* neigh     = (const float*)d_in[1];   // [N,32,128]
    const int*   mask      = (const int*)  d_in[2];   // [N,32]
    const float* W         = (const float*)d_in[3];   // [128,128]
    float* out = (float*)d_out;                        // [N,256]

    const int N = in_sizes[0] / 128;

    // 32 nodes per 256-thread block (4 nodes per warp)
    const int grid = (N + 31) / 32;
    fused_kernel<<<grid, 256>>>(self_vecs, neigh, mask, W, out, N);
}